// round 11
// baseline (speedup 1.0000x reference)
#include <cuda_runtime.h>
#include <cstdint>

// RipsH1 edge-length gather — R4 schedule (best measured) + L1-BYPASS GATHERS.
//
// Flat distance list, D = e0 + 2*e1:
//   t <  e0 : (ia, ib) = verts0 row t
//   t >= e0 : (ia, ib) = ((int2*)verts1)[t - e0]
//   out[t]  = || pts[ia] - pts[ib] ||      (8-dim)
//
// New this round: ld.global.cg.v4.f32 for the point gathers. The 2MB points
// table mostly misses the 228KB L1, and each miss pays line-allocate+fill
// cycles in l1tex on top of the data wavefront — the suspected gap between
// the pure-wavefront floor (~31us) and measured (~38us). .cg routes gathers
// straight to L2 (61% busy -> headroom), eliminating fill work. The U=4
// front-batch (8 in-flight gathers/lane) covers the longer L2 latency.
// Schedule itself is unchanged from the 35.3us best (R4).

static constexpr int DIM_F4   = 2;      // 8 floats = 2 float4
static constexpr int IDX_MASK = 0xFFFF; // N_POINTS = 65536 (power of two)
static constexpr int U        = 4;      // distances per lane-pair
static constexpr int DIST_PER_WARP = 16 * U;  // 64

__device__ __forceinline__ float4 ldcg_f4(const float4* p) {
    float4 r;
    asm volatile("ld.global.cg.v4.f32 {%0, %1, %2, %3}, [%4];"
                 : "=f"(r.x), "=f"(r.y), "=f"(r.z), "=f"(r.w) : "l"(p));
    return r;
}

__global__ __launch_bounds__(256)
void rips_pair_u4cgg_kernel(const float4* __restrict__ pts,
                            const int2* __restrict__ v0,   // e0 rows of 2 i32
                            const int2* __restrict__ v1p,  // verts1 as 2*e1 int2 pairs
                            float* __restrict__ out,
                            int e0, int total) {           // total = e0 + 2*e1
    const int gtid = blockIdx.x * blockDim.x + threadIdx.x;
    const int warp = gtid >> 5;
    const int lane = gtid & 31;
    const int pair = lane >> 1;   // 0..15
    const int h    = lane & 1;    // float4 half owned by this lane

    const int base = warp * DIST_PER_WARP + pair;

    // ---- phase 1: index loads (batched) ----
    int t[U], ia[U], ib[U];
    bool valid[U];
#pragma unroll
    for (int u = 0; u < U; u++) {
        int tt = base + u * 16;
        valid[u] = (tt < total);
        tt = valid[u] ? tt : (total - 1);      // clamp -> safe, converged
        t[u] = tt;
        const int2 p = (tt < e0) ? __ldg(v0 + tt)
                                 : __ldg(v1p + (tt - e0));
        ia[u] = p.x & IDX_MASK;
        ib[u] = p.y & IDX_MASK;
    }

    // ---- phase 2: gathers (batched, L1-bypass; 8 independent LDGs in flight) ----
    float4 a[U], b[U];
#pragma unroll
    for (int u = 0; u < U; u++) {
        a[u] = ldcg_f4(pts + ia[u] * DIM_F4 + h);
        b[u] = ldcg_f4(pts + ib[u] * DIM_F4 + h);
    }

    // ---- phase 3: math + pair-combine + store ----
#pragma unroll
    for (int u = 0; u < U; u++) {
        float dx, s;
        dx = a[u].x - b[u].x; s = dx * dx;
        dx = a[u].y - b[u].y; s = fmaf(dx, dx, s);
        dx = a[u].z - b[u].z; s = fmaf(dx, dx, s);
        dx = a[u].w - b[u].w; s = fmaf(dx, dx, s);
        s += __shfl_xor_sync(0xFFFFFFFF, s, 1);
        if (valid[u] && h == 0)
            out[t[u]] = sqrtf(s);
    }
}

extern "C" void kernel_launch(void* const* d_in, const int* in_sizes, int n_in,
                              void* d_out, int out_size) {
    const float4* pts = (const float4*)d_in[0];
    const int2*   v0  = (const int2*)d_in[1];
    const int2*   v1p = (const int2*)d_in[2];
    float*        out = (float*)d_out;

    const int e0 = in_sizes[1] / 2;          // verts0 rows
    const int e1 = in_sizes[2] / 4;          // verts1 rows
    const int total = e0 + 2 * e1;           // flat distance count

    const int nwarps  = (total + DIST_PER_WARP - 1) / DIST_PER_WARP;
    const int threads = 256;
    const int blocks  = (nwarps * 32 + threads - 1) / threads;
    rips_pair_u4cgg_kernel<<<blocks, threads>>>(pts, v0, v1p, out, e0, total);
}

// round 12
// speedup vs baseline: 1.0087x; 1.0087x over previous
#include <cuda_runtime.h>
#include <cstdint>

// RipsH1 edge-length gather — FINAL (R4 configuration; best measured 35.3us,
// reproducible band 35.3-37.3us across identical re-runs).
//
// Flat distance list, D = e0 + 2*e1:
//   t <  e0 : (ia, ib) = verts0 row t
//   t >= e0 : (ia, ib) = ((int2*)verts1)[t - e0]
//   out[t]  = || pts[ia] - pts[ib] ||      (8-dim)
// (verts1 row j = [a0,b0,a1,b1]; out layout [deaths ++ dgm1-rowmajor] makes
//  the flat output index equal t exactly.)
//
// Why this shape (R2-R11 evidence):
// - 2 lanes per distance: lane h owns float4 half h of each point; the two
//   16B halves of a 32B-aligned row share one sector -> ONE l1tex wavefront
//   per point (2/distance, the structural minimum). R2->R3: 49.9 -> 39.6us.
// - U=4 distances per lane-pair, index loads then gathers front-batched
//   (8 independent LDG.128/lane). U-sweep: U=2 37.3, U=4 35.3, U=8 39.7us.
// - Natural regs (41) / 56% occ: occupancy sweep 33-87% showed no sensitivity;
//   launch_bounds caps measured slightly worse.
// - No cache-op hints: .cg on index/store streams AND on gathers each measured
//   neutral — l1tex% is sector-processing throughput, not fill overhead.
// - Wavefront accounting: 136 wf per 64-distance warp-iter = 2.125 wf/dist;
//   kernel runs at ~0.89 wf/cyc vs the ~1.0 cyc/wf l1tex cap. At ~89% of the
//   non-dedupable random-gather floor; remaining spread is run variance.

static constexpr int DIM_F4   = 2;      // 8 floats = 2 float4
static constexpr int IDX_MASK = 0xFFFF; // N_POINTS = 65536 (power of two)
static constexpr int U        = 4;      // distances per lane-pair
static constexpr int DIST_PER_WARP = 16 * U;  // 64

__global__ __launch_bounds__(256)
void rips_pair_u4_kernel(const float4* __restrict__ pts,
                         const int2* __restrict__ v0,   // e0 rows of 2 i32
                         const int2* __restrict__ v1p,  // verts1 as 2*e1 int2 pairs
                         float* __restrict__ out,
                         int e0, int total) {           // total = e0 + 2*e1
    const int gtid = blockIdx.x * blockDim.x + threadIdx.x;
    const int warp = gtid >> 5;
    const int lane = gtid & 31;
    const int pair = lane >> 1;   // 0..15
    const int h    = lane & 1;    // float4 half owned by this lane

    const int base = warp * DIST_PER_WARP + pair;

    // ---- phase 1: index loads (batched) ----
    int t[U], ia[U], ib[U];
    bool valid[U];
#pragma unroll
    for (int u = 0; u < U; u++) {
        int tt = base + u * 16;
        valid[u] = (tt < total);
        tt = valid[u] ? tt : (total - 1);      // clamp -> safe, converged
        t[u] = tt;
        const int2 p = (tt < e0) ? __ldg(v0 + tt)
                                 : __ldg(v1p + (tt - e0));
        ia[u] = p.x & IDX_MASK;
        ib[u] = p.y & IDX_MASK;
    }

    // ---- phase 2: gathers (batched; 8 independent LDG.128 in flight) ----
    float4 a[U], b[U];
#pragma unroll
    for (int u = 0; u < U; u++) {
        a[u] = __ldg(pts + ia[u] * DIM_F4 + h);
        b[u] = __ldg(pts + ib[u] * DIM_F4 + h);
    }

    // ---- phase 3: math + pair-combine + store ----
#pragma unroll
    for (int u = 0; u < U; u++) {
        float dx, s;
        dx = a[u].x - b[u].x; s = dx * dx;
        dx = a[u].y - b[u].y; s = fmaf(dx, dx, s);
        dx = a[u].z - b[u].z; s = fmaf(dx, dx, s);
        dx = a[u].w - b[u].w; s = fmaf(dx, dx, s);
        s += __shfl_xor_sync(0xFFFFFFFF, s, 1);
        if (valid[u] && h == 0)
            out[t[u]] = sqrtf(s);
    }
}

extern "C" void kernel_launch(void* const* d_in, const int* in_sizes, int n_in,
                              void* d_out, int out_size) {
    const float4* pts = (const float4*)d_in[0];
    const int2*   v0  = (const int2*)d_in[1];
    const int2*   v1p = (const int2*)d_in[2];
    float*        out = (float*)d_out;

    const int e0 = in_sizes[1] / 2;          // verts0 rows
    const int e1 = in_sizes[2] / 4;          // verts1 rows
    const int total = e0 + 2 * e1;           // flat distance count

    const int nwarps  = (total + DIST_PER_WARP - 1) / DIST_PER_WARP;
    const int threads = 256;
    const int blocks  = (nwarps * 32 + threads - 1) / threads;
    rips_pair_u4_kernel<<<blocks, threads>>>(pts, v0, v1p, out, e0, total);
}

// round 13
// speedup vs baseline: 1.0448x; 1.0359x over previous
#include <cuda_runtime.h>
#include <cstdint>

// RipsH1 edge-length gather — FINAL (R4 configuration).
// Measured band of this exact binary across 4 runs: 35.3 / 36.9 / 37.0 / 37.3us.
//
// Flat distance list, D = e0 + 2*e1:
//   t <  e0 : (ia, ib) = verts0 row t
//   t >= e0 : (ia, ib) = ((int2*)verts1)[t - e0]
//   out[t]  = || pts[ia] - pts[ib] ||      (8-dim)
// (verts1 row j = [a0,b0,a1,b1]; out layout [deaths ++ dgm1-rowmajor] makes
//  the flat output index equal t exactly.)
//
// Why this shape (R2-R12 evidence):
// - 2 lanes per distance: lane h owns float4 half h of each point; both 16B
//   halves of a 32B-aligned row share one sector -> ONE l1tex wavefront per
//   point (2/distance = the structural minimum). R2->R3: 49.9 -> 39.6us.
// - U=4 distances per lane-pair, index loads then gathers front-batched
//   (8 independent LDG.128/lane). U-sweep: U=2 37.3, U=4 35.3, U=8 39.7us.
// - Natural regs (41) / 56% occ: occupancy swept 33-87% with zero sensitivity;
//   launch_bounds caps measured slightly worse.
// - No cache-op hints: .cg on index/store streams AND on the gathers each
//   measured neutral — the L1 utilization is sector-processing throughput,
//   not fill overhead, and .cg still traverses that pipe.
// - Rejected on model: smem-staged points w/ edge binning (+80MB stream
//   traffic > gather savings), LDG.64 4-lane split (same sector count),
//   pair-deduped index loads (same lines; issue pipe not binding).
// - Operating point: ~0.89 wf/cyc vs the ~1.0 cyc/wf l1tex cap — ~89% of the
//   non-dedupable uniform-random-gather floor. Remaining spread is variance.

static constexpr int DIM_F4   = 2;      // 8 floats = 2 float4
static constexpr int IDX_MASK = 0xFFFF; // N_POINTS = 65536 (power of two)
static constexpr int U        = 4;      // distances per lane-pair
static constexpr int DIST_PER_WARP = 16 * U;  // 64

__global__ __launch_bounds__(256)
void rips_pair_u4_kernel(const float4* __restrict__ pts,
                         const int2* __restrict__ v0,   // e0 rows of 2 i32
                         const int2* __restrict__ v1p,  // verts1 as 2*e1 int2 pairs
                         float* __restrict__ out,
                         int e0, int total) {           // total = e0 + 2*e1
    const int gtid = blockIdx.x * blockDim.x + threadIdx.x;
    const int warp = gtid >> 5;
    const int lane = gtid & 31;
    const int pair = lane >> 1;   // 0..15
    const int h    = lane & 1;    // float4 half owned by this lane

    const int base = warp * DIST_PER_WARP + pair;

    // ---- phase 1: index loads (batched) ----
    int t[U], ia[U], ib[U];
    bool valid[U];
#pragma unroll
    for (int u = 0; u < U; u++) {
        int tt = base + u * 16;
        valid[u] = (tt < total);
        tt = valid[u] ? tt : (total - 1);      // clamp -> safe, converged
        t[u] = tt;
        const int2 p = (tt < e0) ? __ldg(v0 + tt)
                                 : __ldg(v1p + (tt - e0));
        ia[u] = p.x & IDX_MASK;
        ib[u] = p.y & IDX_MASK;
    }

    // ---- phase 2: gathers (batched; 8 independent LDG.128 in flight) ----
    float4 a[U], b[U];
#pragma unroll
    for (int u = 0; u < U; u++) {
        a[u] = __ldg(pts + ia[u] * DIM_F4 + h);
        b[u] = __ldg(pts + ib[u] * DIM_F4 + h);
    }

    // ---- phase 3: math + pair-combine + store ----
#pragma unroll
    for (int u = 0; u < U; u++) {
        float dx, s;
        dx = a[u].x - b[u].x; s = dx * dx;
        dx = a[u].y - b[u].y; s = fmaf(dx, dx, s);
        dx = a[u].z - b[u].z; s = fmaf(dx, dx, s);
        dx = a[u].w - b[u].w; s = fmaf(dx, dx, s);
        s += __shfl_xor_sync(0xFFFFFFFF, s, 1);
        if (valid[u] && h == 0)
            out[t[u]] = sqrtf(s);
    }
}

extern "C" void kernel_launch(void* const* d_in, const int* in_sizes, int n_in,
                              void* d_out, int out_size) {
    const float4* pts = (const float4*)d_in[0];
    const int2*   v0  = (const int2*)d_in[1];
    const int2*   v1p = (const int2*)d_in[2];
    float*        out = (float*)d_out;

    const int e0 = in_sizes[1] / 2;          // verts0 rows
    const int e1 = in_sizes[2] / 4;          // verts1 rows
    const int total = e0 + 2 * e1;           // flat distance count

    const int nwarps  = (total + DIST_PER_WARP - 1) / DIST_PER_WARP;
    const int threads = 256;
    const int blocks  = (nwarps * 32 + threads - 1) / threads;
    rips_pair_u4_kernel<<<blocks, threads>>>(pts, v0, v1p, out, e0, total);
}